// round 1
// baseline (speedup 1.0000x reference)
#include <cuda_runtime.h>
#include <cstdint>

// Problem constants
#define HID 4096
#define MROWS 2048          // B*S = 4*512
#define NKV 512
#define VECD 64
#define NHEAD 16
#define NDUP 4

// Scratch (device globals: allocation-free rule)
__device__ float g_q[MROWS * HID];     // 32 MB  q projection, (B,S,HID) layout
__device__ float g_attn[MROWS * HID];  // 32 MB  attention output, (B,S,HID)
__device__ float g_ln[MROWS * HID];    // 32 MB  layernorm output
__device__ float g_kT[4 * NHEAD * NKV * VECD]; // 8 MB  [b,h,n,v]
__device__ float g_vT[4 * NHEAD * NKV * VECD]; // 8 MB  [b,h,n,v]

// ---------------------------------------------------------------------------
// SGEMM: C[M,N] = A[M,K] * B[N,K]^T + bias[N]   (both K-major, fp32)
// 128x128x16 tile, 256 threads, 8x8 per thread.
// ---------------------------------------------------------------------------
__global__ __launch_bounds__(256)
void sgemm_nt_kernel(const float* __restrict__ A, const float* __restrict__ B,
                     const float* __restrict__ bias, float* __restrict__ C,
                     int M, int N, int K) {
    constexpr int BM = 128, BN = 128, BK = 16;
    __shared__ float As[BK][BM];
    __shared__ float Bs[BK][BN];

    const int tid = threadIdx.x;
    const int tx = tid & 15;        // 0..15 -> N frag
    const int ty = tid >> 4;        // 0..15 -> M frag
    const int lrow = tid >> 2;      // 0..63
    const int lk   = (tid & 3) * 4; // 0,4,8,12

    const float* Ab = A + (size_t)blockIdx.y * BM * K;
    const float* Bb = B + (size_t)blockIdx.x * BN * K;

    float acc[8][8];
#pragma unroll
    for (int i = 0; i < 8; i++)
#pragma unroll
        for (int j = 0; j < 8; j++) acc[i][j] = 0.f;

    for (int k0 = 0; k0 < K; k0 += BK) {
        float4 a0 = *(const float4*)(Ab + (size_t)lrow * K + k0 + lk);
        float4 a1 = *(const float4*)(Ab + (size_t)(lrow + 64) * K + k0 + lk);
        float4 b0 = *(const float4*)(Bb + (size_t)lrow * K + k0 + lk);
        float4 b1 = *(const float4*)(Bb + (size_t)(lrow + 64) * K + k0 + lk);
        __syncthreads();
        As[lk + 0][lrow] = a0.x; As[lk + 1][lrow] = a0.y;
        As[lk + 2][lrow] = a0.z; As[lk + 3][lrow] = a0.w;
        As[lk + 0][lrow + 64] = a1.x; As[lk + 1][lrow + 64] = a1.y;
        As[lk + 2][lrow + 64] = a1.z; As[lk + 3][lrow + 64] = a1.w;
        Bs[lk + 0][lrow] = b0.x; Bs[lk + 1][lrow] = b0.y;
        Bs[lk + 2][lrow] = b0.z; Bs[lk + 3][lrow] = b0.w;
        Bs[lk + 0][lrow + 64] = b1.x; Bs[lk + 1][lrow + 64] = b1.y;
        Bs[lk + 2][lrow + 64] = b1.z; Bs[lk + 3][lrow + 64] = b1.w;
        __syncthreads();
#pragma unroll
        for (int kk = 0; kk < BK; kk++) {
            float a[8], b[8];
            *(float4*)&a[0] = *(const float4*)&As[kk][ty * 8];
            *(float4*)&a[4] = *(const float4*)&As[kk][ty * 8 + 4];
            *(float4*)&b[0] = *(const float4*)&Bs[kk][tx * 8];
            *(float4*)&b[4] = *(const float4*)&Bs[kk][tx * 8 + 4];
#pragma unroll
            for (int i = 0; i < 8; i++)
#pragma unroll
                for (int j = 0; j < 8; j++)
                    acc[i][j] += a[i] * b[j];
        }
    }

    const int row0 = blockIdx.y * BM + ty * 8;
    const int col0 = blockIdx.x * BN + tx * 8;
    float bb[8];
#pragma unroll
    for (int j = 0; j < 8; j++) bb[j] = bias[col0 + j];
#pragma unroll
    for (int i = 0; i < 8; i++) {
        float4 o0, o1;
        o0.x = acc[i][0] + bb[0]; o0.y = acc[i][1] + bb[1];
        o0.z = acc[i][2] + bb[2]; o0.w = acc[i][3] + bb[3];
        o1.x = acc[i][4] + bb[4]; o1.y = acc[i][5] + bb[5];
        o1.z = acc[i][6] + bb[6]; o1.w = acc[i][7] + bb[7];
        float* cp = C + (size_t)(row0 + i) * N + col0;
        *(float4*)cp = o0;
        *(float4*)(cp + 4) = o1;
    }
}

// ---------------------------------------------------------------------------
// Transpose K/V: [b,n, v*16+h] -> [b,h,n,v]  (coalesced writes)
// ---------------------------------------------------------------------------
__global__ __launch_bounds__(256)
void transpose_kv_kernel(const float* __restrict__ keys, const float* __restrict__ vals,
                         float* __restrict__ kT, float* __restrict__ vT) {
    int idx = blockIdx.x * 256 + threadIdx.x; // over 4*16*512*64 = 2M
    int v = idx & 63;
    int n = (idx >> 6) & 511;
    int h = (idx >> 15) & 15;
    int b = idx >> 19;
    size_t src = (size_t)(b * NKV + n) * (VECD * NHEAD) + v * NHEAD + h;
    kT[idx] = keys[src];
    vT[idx] = vals[src];
}

// ---------------------------------------------------------------------------
// Attention: per block (b,h, 32 sdup rows). Exact two-pass softmax in smem.
//  q_att[b,h,sdup,v] = q[b, sdup/4, (sdup%4)*1024 + v*16 + h]
//  attn[b, s, h*256 + d*64 + vec]
// ---------------------------------------------------------------------------
#define ATTN_SMEM_FLOATS (2048 + 64*68 + 32*512)
__global__ __launch_bounds__(256)
void attn_kernel(const float* __restrict__ q, const float* __restrict__ kT,
                 const float* __restrict__ vT, float* __restrict__ outp) {
    extern __shared__ float sm[];
    float* q_s  = sm;                 // 32*64
    float* kv_s = sm + 2048;          // 64*68 (padded)
    float* sc   = sm + 2048 + 64*68;  // 32*512

    const int tid  = threadIdx.x;
    const int bh   = blockIdx.y;
    const int b    = bh >> 4;
    const int h    = bh & 15;
    const int tile = blockIdx.x;      // 0..63, 32 sdup rows each

    // load q tile
    for (int i = tid; i < 32 * 64; i += 256) {
        int r = i >> 6, v = i & 63;
        int sdup = tile * 32 + r;
        int s = sdup >> 2, d = sdup & 3;
        q_s[i] = q[(size_t)(b * 512 + s) * HID + d * 1024 + v * 16 + h];
    }

    const float* kb = kT + (size_t)(b * NHEAD + h) * NKV * VECD;
    const float* vb = vT + (size_t)(b * NHEAD + h) * NKV * VECD;

    const int r  = tid >> 3;  // 0..31  (row)
    const int ng = tid & 7;   // 0..7   (n-group / vec-group)

    // ---- scores ----
    for (int nt = 0; nt < 8; nt++) {
        __syncthreads();
        for (int i = tid; i < 64 * 64; i += 256) {
            int n = i >> 6, v = i & 63;
            kv_s[n * 68 + v] = kb[(size_t)(nt * 64 + n) * 64 + v];
        }
        __syncthreads();
        float sa[8];
#pragma unroll
        for (int j = 0; j < 8; j++) sa[j] = 0.f;
#pragma unroll
        for (int v4 = 0; v4 < 16; v4++) {
            float4 qv = *(const float4*)&q_s[r * 64 + v4 * 4];
#pragma unroll
            for (int j = 0; j < 8; j++) {
                float4 kv = *(const float4*)&kv_s[(ng * 8 + j) * 68 + v4 * 4];
                sa[j] += qv.x * kv.x + qv.y * kv.y + qv.z * kv.z + qv.w * kv.w;
            }
        }
#pragma unroll
        for (int j = 0; j < 8; j++)
            sc[r * 512 + nt * 64 + ng * 8 + j] = sa[j] * 0.125f;
    }
    __syncthreads();

    // ---- softmax (warp handles 4 rows) ----
    {
        int w = tid >> 5, lane = tid & 31;
        for (int rr = 0; rr < 4; rr++) {
            int rw = w * 4 + rr;
            float v[16];
            float m = -1e30f;
#pragma unroll
            for (int i = 0; i < 16; i++) {
                v[i] = sc[rw * 512 + i * 32 + lane];
                m = fmaxf(m, v[i]);
            }
#pragma unroll
            for (int o = 16; o > 0; o >>= 1)
                m = fmaxf(m, __shfl_xor_sync(0xffffffffu, m, o));
            float ssum = 0.f;
#pragma unroll
            for (int i = 0; i < 16; i++) { v[i] = __expf(v[i] - m); ssum += v[i]; }
#pragma unroll
            for (int o = 16; o > 0; o >>= 1)
                ssum += __shfl_xor_sync(0xffffffffu, ssum, o);
            float inv = 1.f / ssum;
#pragma unroll
            for (int i = 0; i < 16; i++)
                sc[rw * 512 + i * 32 + lane] = v[i] * inv;
        }
    }

    // ---- out = probs @ V ----
    float acc[8];
#pragma unroll
    for (int j = 0; j < 8; j++) acc[j] = 0.f;
    for (int nt = 0; nt < 8; nt++) {
        __syncthreads();
        for (int i = tid; i < 64 * 64; i += 256) {
            int n = i >> 6, v = i & 63;
            kv_s[n * 68 + v] = vb[(size_t)(nt * 64 + n) * 64 + v];
        }
        __syncthreads();
#pragma unroll
        for (int n = 0; n < 64; n++) {
            float p = sc[r * 512 + nt * 64 + n];
            float4 va = *(const float4*)&kv_s[n * 68 + ng * 8];
            float4 vb4 = *(const float4*)&kv_s[n * 68 + ng * 8 + 4];
            acc[0] += p * va.x; acc[1] += p * va.y;
            acc[2] += p * va.z; acc[3] += p * va.w;
            acc[4] += p * vb4.x; acc[5] += p * vb4.y;
            acc[6] += p * vb4.z; acc[7] += p * vb4.w;
        }
    }
    int sdup = tile * 32 + r;
    int s = sdup >> 2, d = sdup & 3;
    float* op = outp + (size_t)(b * 512 + s) * HID + h * 256 + d * 64 + ng * 8;
    *(float4*)op       = make_float4(acc[0], acc[1], acc[2], acc[3]);
    *(float4*)(op + 4) = make_float4(acc[4], acc[5], acc[6], acc[7]);
}

// ---------------------------------------------------------------------------
// LayerNorm over hidden=4096 (biased variance, torch semantics)
// ---------------------------------------------------------------------------
__global__ __launch_bounds__(256)
void ln_kernel(const float* __restrict__ x, const float* __restrict__ gam,
               const float* __restrict__ bet, float* __restrict__ y) {
    __shared__ float xs[HID];
    __shared__ float red[8];
    __shared__ float red2[8];
    const int row = blockIdx.x;
    const int tid = threadIdx.x;
    const int lane = tid & 31, w = tid >> 5;
    const float* xr = x + (size_t)row * HID;

    float lsum = 0.f;
    for (int i = tid; i < HID; i += 256) {
        float v = xr[i];
        xs[i] = v;
        lsum += v;
    }
#pragma unroll
    for (int o = 16; o > 0; o >>= 1) lsum += __shfl_xor_sync(0xffffffffu, lsum, o);
    if (lane == 0) red[w] = lsum;
    __syncthreads();
    float tot = 0.f;
#pragma unroll
    for (int j = 0; j < 8; j++) tot += red[j];
    float mu = tot * (1.f / HID);

    float lv = 0.f;
    for (int i = tid; i < HID; i += 256) {
        float d = xs[i] - mu;
        lv += d * d;
    }
#pragma unroll
    for (int o = 16; o > 0; o >>= 1) lv += __shfl_xor_sync(0xffffffffu, lv, o);
    if (lane == 0) red2[w] = lv;
    __syncthreads();
    float tv = 0.f;
#pragma unroll
    for (int j = 0; j < 8; j++) tv += red2[j];
    float inv = rsqrtf(tv * (1.f / HID) + 1e-12f);

    for (int i = tid; i < HID; i += 256)
        y[(size_t)row * HID + i] = (xs[i] - mu) * inv * gam[i] + bet[i];
}

// ---------------------------------------------------------------------------
extern "C" void kernel_launch(void* const* d_in, const int* in_sizes, int n_in,
                              void* d_out, int out_size) {
    const float* emb  = (const float*)d_in[0];
    const float* keys = (const float*)d_in[1];
    const float* vals = (const float*)d_in[2];
    const float* Wq   = (const float*)d_in[3];
    const float* bq   = (const float*)d_in[4];
    const float* Wre  = (const float*)d_in[5];
    const float* bre  = (const float*)d_in[6];
    const float* ln_g = (const float*)d_in[7];
    const float* ln_b = (const float*)d_in[8];
    float* out = (float*)d_out;

    float *qbuf, *abuf, *lbuf, *kTb, *vTb;
    cudaGetSymbolAddress((void**)&qbuf, g_q);
    cudaGetSymbolAddress((void**)&abuf, g_attn);
    cudaGetSymbolAddress((void**)&lbuf, g_ln);
    cudaGetSymbolAddress((void**)&kTb, g_kT);
    cudaGetSymbolAddress((void**)&vTb, g_vT);

    cudaFuncSetAttribute(attn_kernel, cudaFuncAttributeMaxDynamicSharedMemorySize,
                         ATTN_SMEM_FLOATS * sizeof(float));

    // 1) q projection: (2048,4096) @ Wq^T + bq
    sgemm_nt_kernel<<<dim3(HID / 128, MROWS / 128), 256>>>(emb, Wq, bq, qbuf,
                                                           MROWS, HID, HID);
    // 2) K/V transpose to [b,h,n,v]
    transpose_kv_kernel<<<(4 * NHEAD * NKV * VECD) / 256, 256>>>(keys, vals, kTb, vTb);
    // 3) attention
    attn_kernel<<<dim3(64, 64), 256, ATTN_SMEM_FLOATS * sizeof(float)>>>(qbuf, kTb, vTb, abuf);
    // 4) layernorm
    ln_kernel<<<MROWS, 256>>>(abuf, ln_g, ln_b, lbuf);
    // 5) output projection
    sgemm_nt_kernel<<<dim3(HID / 128, MROWS / 128), 256>>>(lbuf, Wre, bre, out,
                                                           MROWS, HID, HID);
}

// round 3
// speedup vs baseline: 1.4762x; 1.4762x over previous
#include <cuda_runtime.h>
#include <cuda_bf16.h>
#include <cstdint>

#define HID 4096
#define MROWS 2048
#define NKV 512
#define VECD 64
#define NHEAD 16

// ---------------- scratch (device globals; allocation-free rule) ----------
__device__ float g_q[MROWS * HID];
__device__ float g_attn[MROWS * HID];
__device__ float g_kT[4 * NHEAD * NKV * VECD];
__device__ float g_vT[4 * NHEAD * NKV * VECD];
__device__ __nv_bfloat16 g_ehi[MROWS * HID], g_elo[MROWS * HID];
__device__ __nv_bfloat16 g_lnhi[MROWS * HID], g_lnlo[MROWS * HID];
__device__ __nv_bfloat16 g_wqhi[HID * HID], g_wqlo[HID * HID];
__device__ __nv_bfloat16 g_wrehi[HID * HID], g_wrelo[HID * HID];

// ---------------- PTX helpers ----------------------------------------------
__device__ __forceinline__ uint32_t smem_u32(const void* p) {
    uint32_t a;
    asm("{ .reg .u64 t; cvta.to.shared.u64 t, %1; cvt.u32.u64 %0, t; }" : "=r"(a) : "l"(p));
    return a;
}
#define CP_ASYNC16(dst, src) \
    asm volatile("cp.async.cg.shared.global [%0], [%1], 16;" :: "r"(dst), "l"(src))
#define CP_COMMIT() asm volatile("cp.async.commit_group;" ::: "memory")
#define CP_WAIT2()  asm volatile("cp.async.wait_group 2;" ::: "memory")

#define LDSM4(r0, r1, r2, r3, addr)                                          \
    asm volatile("ldmatrix.sync.aligned.m8n8.x4.shared.b16 {%0,%1,%2,%3}, [%4];" \
                 : "=r"(r0), "=r"(r1), "=r"(r2), "=r"(r3) : "r"(addr))
#define LDSM2(r0, r1, addr)                                                  \
    asm volatile("ldmatrix.sync.aligned.m8n8.x2.shared.b16 {%0,%1}, [%2];"   \
                 : "=r"(r0), "=r"(r1) : "r"(addr))

__device__ __forceinline__ void mma16816(float* c, const uint32_t* a, const uint32_t* b) {
    asm volatile(
        "mma.sync.aligned.m16n8k16.row.col.f32.bf16.bf16.f32 "
        "{%0,%1,%2,%3}, {%4,%5,%6,%7}, {%8,%9}, {%0,%1,%2,%3};"
        : "+f"(c[0]), "+f"(c[1]), "+f"(c[2]), "+f"(c[3])
        : "r"(a[0]), "r"(a[1]), "r"(a[2]), "r"(a[3]), "r"(b[0]), "r"(b[1]));
}

// swizzled byte offset within a 128x32 bf16 tile (64B rows, 16B chunks)
__device__ __forceinline__ uint32_t sw_off(int r, int c16) {
    return (uint32_t)(r * 64 + ((c16 ^ ((r >> 1) & 3)) << 4));
}

// ---------------------------------------------------------------------------
// bf16-split tensor-core GEMM: C[M,N] = (Ahi+Alo)[M,K] @ (Bhi+Blo)[N,K]^T + bias
// 128x128 CTA tile, BK=32, 3-stage cp.async pipeline, 8 warps (2m x 4n).
// ---------------------------------------------------------------------------
#define GEMM_STAGE_BYTES 32768        // 4 tiles x 8192
#define GEMM_SMEM (3 * GEMM_STAGE_BYTES)
__global__ __launch_bounds__(256, 2)
void gemm_mma_kernel(const __nv_bfloat16* __restrict__ Ahi, const __nv_bfloat16* __restrict__ Alo,
                     const __nv_bfloat16* __restrict__ Bhi, const __nv_bfloat16* __restrict__ Blo,
                     const float* __restrict__ bias, float* __restrict__ C,
                     int M, int N, int K) {
    extern __shared__ char smraw[];
    const uint32_t sbase = smem_u32(smraw);
    const int tid = threadIdx.x;
    const int lane = tid & 31;
    const int warp = tid >> 5;
    const int wm = warp & 1;          // 0..1  -> 64-row slab
    const int wn = warp >> 1;         // 0..3  -> 32-col slab

    const int row0 = blockIdx.y * 128;
    const int col0 = blockIdx.x * 128;
    const __nv_bfloat16* srcs[4] = {Ahi + (size_t)row0 * K, Alo + (size_t)row0 * K,
                                    Bhi + (size_t)col0 * K, Blo + (size_t)col0 * K};
    const int nk = K / 32;

    // load chunk kc into stage st
    auto load_stage = [&](int kc, int st) {
        const int kbase = kc * 32;
        const uint32_t stg = sbase + st * GEMM_STAGE_BYTES;
#pragma unroll
        for (int t = 0; t < 4; t++) {
            const __nv_bfloat16* s = srcs[t];
#pragma unroll
            for (int it = 0; it < 2; it++) {
                int idx = tid + it * 256;      // 0..511
                int r = idx >> 2, c = idx & 3;
                uint32_t dst = stg + t * 8192 + sw_off(r, c);
                CP_ASYNC16(dst, s + (size_t)r * K + kbase + c * 8);
            }
        }
    };

    float acc[4][4][4];
#pragma unroll
    for (int i = 0; i < 4; i++)
#pragma unroll
        for (int j = 0; j < 4; j++)
#pragma unroll
            for (int k = 0; k < 4; k++) acc[i][j][k] = 0.f;

    load_stage(0, 0); CP_COMMIT();
    load_stage(1, 1); CP_COMMIT();

    for (int kc = 0; kc < nk; kc++) {
        const int ps = kc + 2;
        if (ps < nk) load_stage(ps, ps % 3);
        CP_COMMIT();
        CP_WAIT2();
        __syncthreads();

        const uint32_t stg = sbase + (kc % 3) * GEMM_STAGE_BYTES;
        const uint32_t sAhi = stg, sAlo = stg + 8192, sBhi = stg + 16384, sBlo = stg + 24576;

#pragma unroll
        for (int ks = 0; ks < 2; ks++) {
            uint32_t ah[4][4], al[4][4], bf[4][2];
            const int arow = lane & 15;
            const int ac = ks * 2 + (lane >> 4);
            const int brow = lane & 7;
            const int bc = ks * 2 + ((lane >> 3) & 1);
#pragma unroll
            for (int mt = 0; mt < 4; mt++) {
                int r = wm * 64 + mt * 16 + arow;
                LDSM4(ah[mt][0], ah[mt][1], ah[mt][2], ah[mt][3], sAhi + sw_off(r, ac));
            }
#pragma unroll
            for (int mt = 0; mt < 4; mt++) {
                int r = wm * 64 + mt * 16 + arow;
                LDSM4(al[mt][0], al[mt][1], al[mt][2], al[mt][3], sAlo + sw_off(r, ac));
            }
#pragma unroll
            for (int nt = 0; nt < 4; nt++) {
                int r = wn * 32 + nt * 8 + brow;
                LDSM2(bf[nt][0], bf[nt][1], sBhi + sw_off(r, bc));
            }
#pragma unroll
            for (int mt = 0; mt < 4; mt++)
#pragma unroll
                for (int nt = 0; nt < 4; nt++) {
                    mma16816(acc[mt][nt], ah[mt], bf[nt]);   // hi*hi
                    mma16816(acc[mt][nt], al[mt], bf[nt]);   // lo*hi
                }
#pragma unroll
            for (int nt = 0; nt < 4; nt++) {
                int r = wn * 32 + nt * 8 + brow;
                LDSM2(bf[nt][0], bf[nt][1], sBlo + sw_off(r, bc));
            }
#pragma unroll
            for (int mt = 0; mt < 4; mt++)
#pragma unroll
                for (int nt = 0; nt < 4; nt++)
                    mma16816(acc[mt][nt], ah[mt], bf[nt]);   // hi*lo
        }
        __syncthreads();
    }

    // epilogue
#pragma unroll
    for (int mt = 0; mt < 4; mt++) {
        int r = row0 + wm * 64 + mt * 16 + (lane >> 2);
#pragma unroll
        for (int nt = 0; nt < 4; nt++) {
            int c = col0 + wn * 32 + nt * 8 + (lane & 3) * 2;
            float b0 = __ldg(bias + c), b1 = __ldg(bias + c + 1);
            float2 v0 = make_float2(acc[mt][nt][0] + b0, acc[mt][nt][1] + b1);
            float2 v1 = make_float2(acc[mt][nt][2] + b0, acc[mt][nt][3] + b1);
            *(float2*)(C + (size_t)r * N + c) = v0;
            *(float2*)(C + (size_t)(r + 8) * N + c) = v1;
        }
    }
}

// ---------------------------------------------------------------------------
// fp32 -> bf16 hi/lo split
// ---------------------------------------------------------------------------
__global__ __launch_bounds__(256)
void split_kernel(const float4* __restrict__ x, __nv_bfloat162* __restrict__ hi,
                  __nv_bfloat162* __restrict__ lo, int n4) {
    int i = blockIdx.x * 256 + threadIdx.x;
    if (i >= n4) return;
    float4 v = x[i];
    __nv_bfloat16 h0 = __float2bfloat16(v.x), h1 = __float2bfloat16(v.y);
    __nv_bfloat16 h2 = __float2bfloat16(v.z), h3 = __float2bfloat16(v.w);
    __nv_bfloat16 l0 = __float2bfloat16(v.x - __bfloat162float(h0));
    __nv_bfloat16 l1 = __float2bfloat16(v.y - __bfloat162float(h1));
    __nv_bfloat16 l2 = __float2bfloat16(v.z - __bfloat162float(h2));
    __nv_bfloat16 l3 = __float2bfloat16(v.w - __bfloat162float(h3));
    hi[2 * i] = __halves2bfloat162(h0, h1);
    hi[2 * i + 1] = __halves2bfloat162(h2, h3);
    lo[2 * i] = __halves2bfloat162(l0, l1);
    lo[2 * i + 1] = __halves2bfloat162(l2, l3);
}

// ---------------------------------------------------------------------------
// Transpose K/V: [b,n, v*16+h] -> [b,h,n,v]
// ---------------------------------------------------------------------------
__global__ __launch_bounds__(256)
void transpose_kv_kernel(const float* __restrict__ keys, const float* __restrict__ vals,
                         float* __restrict__ kT, float* __restrict__ vT) {
    int idx = blockIdx.x * 256 + threadIdx.x;
    int v = idx & 63;
    int n = (idx >> 6) & 511;
    int h = (idx >> 15) & 15;
    int b = idx >> 19;
    size_t src = (size_t)(b * NKV + n) * (VECD * NHEAD) + v * NHEAD + h;
    kT[idx] = keys[src];
    vT[idx] = vals[src];
}

// ---------------------------------------------------------------------------
// Attention (fp32, smem tiles)
// ---------------------------------------------------------------------------
#define ATTN_SMEM_FLOATS (2048 + 64 * 68 + 32 * 512)
__global__ __launch_bounds__(256)
void attn_kernel(const float* __restrict__ q, const float* __restrict__ kT,
                 const float* __restrict__ vT, float* __restrict__ outp) {
    extern __shared__ float sm[];
    float* q_s = sm;
    float* kv_s = sm + 2048;
    float* sc = sm + 2048 + 64 * 68;

    const int tid = threadIdx.x;
    const int bh = blockIdx.y;
    const int b = bh >> 4;
    const int h = bh & 15;
    const int tile = blockIdx.x;

    for (int i = tid; i < 32 * 64; i += 256) {
        int r = i >> 6, v = i & 63;
        int sdup = tile * 32 + r;
        int s = sdup >> 2, d = sdup & 3;
        q_s[i] = q[(size_t)(b * 512 + s) * HID + d * 1024 + v * 16 + h];
    }

    const float* kb = kT + (size_t)(b * NHEAD + h) * NKV * VECD;
    const float* vb = vT + (size_t)(b * NHEAD + h) * NKV * VECD;

    const int r = tid >> 3;
    const int ng = tid & 7;

    for (int nt = 0; nt < 8; nt++) {
        __syncthreads();
        for (int i = tid; i < 64 * 64; i += 256) {
            int n = i >> 6, v = i & 63;
            kv_s[n * 68 + v] = kb[(size_t)(nt * 64 + n) * 64 + v];
        }
        __syncthreads();
        float sa[8];
#pragma unroll
        for (int j = 0; j < 8; j++) sa[j] = 0.f;
#pragma unroll
        for (int v4 = 0; v4 < 16; v4++) {
            float4 qv = *(const float4*)&q_s[r * 64 + v4 * 4];
#pragma unroll
            for (int j = 0; j < 8; j++) {
                float4 kv = *(const float4*)&kv_s[(ng * 8 + j) * 68 + v4 * 4];
                sa[j] += qv.x * kv.x + qv.y * kv.y + qv.z * kv.z + qv.w * kv.w;
            }
        }
#pragma unroll
        for (int j = 0; j < 8; j++)
            sc[r * 512 + nt * 64 + ng * 8 + j] = sa[j] * 0.125f;
    }
    __syncthreads();

    {
        int w = tid >> 5, lane = tid & 31;
        for (int rr = 0; rr < 4; rr++) {
            int rw = w * 4 + rr;
            float v[16];
            float m = -1e30f;
#pragma unroll
            for (int i = 0; i < 16; i++) {
                v[i] = sc[rw * 512 + i * 32 + lane];
                m = fmaxf(m, v[i]);
            }
#pragma unroll
            for (int o = 16; o > 0; o >>= 1)
                m = fmaxf(m, __shfl_xor_sync(0xffffffffu, m, o));
            float ssum = 0.f;
#pragma unroll
            for (int i = 0; i < 16; i++) { v[i] = __expf(v[i] - m); ssum += v[i]; }
#pragma unroll
            for (int o = 16; o > 0; o >>= 1)
                ssum += __shfl_xor_sync(0xffffffffu, ssum, o);
            float inv = 1.f / ssum;
#pragma unroll
            for (int i = 0; i < 16; i++)
                sc[rw * 512 + i * 32 + lane] = v[i] * inv;
        }
    }

    float acc[8];
#pragma unroll
    for (int j = 0; j < 8; j++) acc[j] = 0.f;
    for (int nt = 0; nt < 8; nt++) {
        __syncthreads();
        for (int i = tid; i < 64 * 64; i += 256) {
            int n = i >> 6, v = i & 63;
            kv_s[n * 68 + v] = vb[(size_t)(nt * 64 + n) * 64 + v];
        }
        __syncthreads();
#pragma unroll
        for (int n = 0; n < 64; n++) {
            float p = sc[r * 512 + nt * 64 + n];
            float4 va = *(const float4*)&kv_s[n * 68 + ng * 8];
            float4 vb4 = *(const float4*)&kv_s[n * 68 + ng * 8 + 4];
            acc[0] += p * va.x; acc[1] += p * va.y;
            acc[2] += p * va.z; acc[3] += p * va.w;
            acc[4] += p * vb4.x; acc[5] += p * vb4.y;
            acc[6] += p * vb4.z; acc[7] += p * vb4.w;
        }
    }
    int sdup = tile * 32 + r;
    int s = sdup >> 2, d = sdup & 3;
    float* op = outp + (size_t)(b * 512 + s) * HID + h * 256 + d * 64 + ng * 8;
    *(float4*)op = make_float4(acc[0], acc[1], acc[2], acc[3]);
    *(float4*)(op + 4) = make_float4(acc[4], acc[5], acc[6], acc[7]);
}

// ---------------------------------------------------------------------------
// LayerNorm fused with bf16 hi/lo split output
// ---------------------------------------------------------------------------
__global__ __launch_bounds__(256)
void ln_split_kernel(const float* __restrict__ x, const float* __restrict__ gam,
                     const float* __restrict__ bet, __nv_bfloat16* __restrict__ hi,
                     __nv_bfloat16* __restrict__ lo) {
    __shared__ float xs[HID];
    __shared__ float red[8];
    __shared__ float red2[8];
    const int row = blockIdx.x;
    const int tid = threadIdx.x;
    const int lane = tid & 31, w = tid >> 5;
    const float* xr = x + (size_t)row * HID;

    float lsum = 0.f;
    for (int i = tid; i < HID; i += 256) {
        float v = xr[i];
        xs[i] = v;
        lsum += v;
    }
#pragma unroll
    for (int o = 16; o > 0; o >>= 1) lsum += __shfl_xor_sync(0xffffffffu, lsum, o);
    if (lane == 0) red[w] = lsum;
    __syncthreads();
    float tot = 0.f;
#pragma unroll
    for (int j = 0; j < 8; j++) tot += red[j];
    float mu = tot * (1.f / HID);

    float lv = 0.f;
    for (int i = tid; i < HID; i += 256) {
        float d = xs[i] - mu;
        lv += d * d;
    }
#pragma unroll
    for (int o = 16; o > 0; o >>= 1) lv += __shfl_xor_sync(0xffffffffu, lv, o);
    if (lane == 0) red2[w] = lv;
    __syncthreads();
    float tv = 0.f;
#pragma unroll
    for (int j = 0; j < 8; j++) tv += red2[j];
    float inv = rsqrtf(tv * (1.f / HID) + 1e-12f);

    for (int i = tid * 4; i < HID; i += 1024) {
        float4 xv = *(const float4*)&xs[i];
        float4 gv = *(const float4*)&gam[i];
        float4 bv = *(const float4*)&bet[i];
        float y0 = (xv.x - mu) * inv * gv.x + bv.x;
        float y1 = (xv.y - mu) * inv * gv.y + bv.y;
        float y2 = (xv.z - mu) * inv * gv.z + bv.z;
        float y3 = (xv.w - mu) * inv * gv.w + bv.w;
        __nv_bfloat16 h0 = __float2bfloat16(y0), h1 = __float2bfloat16(y1);
        __nv_bfloat16 h2 = __float2bfloat16(y2), h3 = __float2bfloat16(y3);
        __nv_bfloat16 l0 = __float2bfloat16(y0 - __bfloat162float(h0));
        __nv_bfloat16 l1 = __float2bfloat16(y1 - __bfloat162float(h1));
        __nv_bfloat16 l2 = __float2bfloat16(y2 - __bfloat162float(h2));
        __nv_bfloat16 l3 = __float2bfloat16(y3 - __bfloat162float(h3));
        size_t o = (size_t)row * HID + i;
        *(__nv_bfloat162*)(hi + o) = __halves2bfloat162(h0, h1);
        *(__nv_bfloat162*)(hi + o + 2) = __halves2bfloat162(h2, h3);
        *(__nv_bfloat162*)(lo + o) = __halves2bfloat162(l0, l1);
        *(__nv_bfloat162*)(lo + o + 2) = __halves2bfloat162(l2, l3);
    }
}

// ---------------------------------------------------------------------------
extern "C" void kernel_launch(void* const* d_in, const int* in_sizes, int n_in,
                              void* d_out, int out_size) {
    const float* emb  = (const float*)d_in[0];
    const float* keys = (const float*)d_in[1];
    const float* vals = (const float*)d_in[2];
    const float* Wq   = (const float*)d_in[3];
    const float* bq   = (const float*)d_in[4];
    const float* Wre  = (const float*)d_in[5];
    const float* bre  = (const float*)d_in[6];
    const float* ln_g = (const float*)d_in[7];
    const float* ln_b = (const float*)d_in[8];
    float* out = (float*)d_out;

    float *qbuf, *abuf, *kTb, *vTb;
    __nv_bfloat16 *ehi, *elo, *lnhi, *lnlo, *wqhi, *wqlo, *wrehi, *wrelo;
    cudaGetSymbolAddress((void**)&qbuf, g_q);
    cudaGetSymbolAddress((void**)&abuf, g_attn);
    cudaGetSymbolAddress((void**)&kTb, g_kT);
    cudaGetSymbolAddress((void**)&vTb, g_vT);
    cudaGetSymbolAddress((void**)&ehi, g_ehi);
    cudaGetSymbolAddress((void**)&elo, g_elo);
    cudaGetSymbolAddress((void**)&lnhi, g_lnhi);
    cudaGetSymbolAddress((void**)&lnlo, g_lnlo);
    cudaGetSymbolAddress((void**)&wqhi, g_wqhi);
    cudaGetSymbolAddress((void**)&wqlo, g_wqlo);
    cudaGetSymbolAddress((void**)&wrehi, g_wrehi);
    cudaGetSymbolAddress((void**)&wrelo, g_wrelo);

    cudaFuncSetAttribute(attn_kernel, cudaFuncAttributeMaxDynamicSharedMemorySize,
                         ATTN_SMEM_FLOATS * sizeof(float));
    cudaFuncSetAttribute(gemm_mma_kernel, cudaFuncAttributeMaxDynamicSharedMemorySize,
                         GEMM_SMEM);

    // split conversions
    split_kernel<<<(MROWS * HID / 4 + 255) / 256, 256>>>((const float4*)emb,
        (__nv_bfloat162*)ehi, (__nv_bfloat162*)elo, MROWS * HID / 4);
    split_kernel<<<(HID * HID / 4 + 255) / 256, 256>>>((const float4*)Wq,
        (__nv_bfloat162*)wqhi, (__nv_bfloat162*)wqlo, HID * HID / 4);
    split_kernel<<<(HID * HID / 4 + 255) / 256, 256>>>((const float4*)Wre,
        (__nv_bfloat162*)wrehi, (__nv_bfloat162*)wrelo, HID * HID / 4);

    // 1) q projection (tensor cores)
    gemm_mma_kernel<<<dim3(HID / 128, MROWS / 128), 256, GEMM_SMEM>>>(
        ehi, elo, wqhi, wqlo, bq, qbuf, MROWS, HID, HID);
    // 2) K/V transpose
    transpose_kv_kernel<<<(4 * NHEAD * NKV * VECD) / 256, 256>>>(keys, vals, kTb, vTb);
    // 3) attention
    attn_kernel<<<dim3(64, 64), 256, ATTN_SMEM_FLOATS * sizeof(float)>>>(qbuf, kTb, vTb, abuf);
    // 4) layernorm + split
    ln_split_kernel<<<MROWS, 256>>>(abuf, ln_g, ln_b, lnhi, lnlo);
    // 5) output projection (tensor cores)
    gemm_mma_kernel<<<dim3(HID / 128, MROWS / 128), 256, GEMM_SMEM>>>(
        lnhi, lnlo, wrehi, wrelo, bre, out, MROWS, HID, HID);
}

// round 4
// speedup vs baseline: 6.1718x; 4.1809x over previous
#include <cuda_runtime.h>
#include <cuda_bf16.h>
#include <cstdint>

#define HID 4096
#define MROWS 2048
#define NKV 512
#define VECD 64
#define NHEAD 16
#define NBH 64            // B * NHEAD
#define SDUP 2048         // S * DUP per (b,h)

// ---------------- scratch (device globals; allocation-free rule) ----------
__device__ float g_q[MROWS * HID];
__device__ float g_attnT[NBH * SDUP * VECD];       // attention out, [bh][sdup][vec]
__device__ __nv_bfloat16 g_qhi[NBH * SDUP * VECD], g_qlo[NBH * SDUP * VECD];
__device__ __nv_bfloat16 g_khi[NBH * NKV * VECD], g_klo[NBH * NKV * VECD];
__device__ __nv_bfloat16 g_vhi[NBH * VECD * NKV], g_vlo[NBH * VECD * NKV];  // [bh][vec][n]
__device__ __nv_bfloat16 g_ehi[MROWS * HID], g_elo[MROWS * HID];
__device__ __nv_bfloat16 g_lnhi[MROWS * HID], g_lnlo[MROWS * HID];
__device__ __nv_bfloat16 g_wqhi[HID * HID], g_wqlo[HID * HID];
__device__ __nv_bfloat16 g_wrehi[HID * HID], g_wrelo[HID * HID];

// ---------------- PTX helpers ----------------------------------------------
__device__ __forceinline__ uint32_t smem_u32(const void* p) {
    uint32_t a;
    asm("{ .reg .u64 t; cvta.to.shared.u64 t, %1; cvt.u32.u64 %0, t; }" : "=r"(a) : "l"(p));
    return a;
}
#define CP_ASYNC16(dst, src) \
    asm volatile("cp.async.cg.shared.global [%0], [%1], 16;" :: "r"(dst), "l"(src))
#define CP_COMMIT() asm volatile("cp.async.commit_group;" ::: "memory")
#define CP_WAIT2()  asm volatile("cp.async.wait_group 2;" ::: "memory")
#define CP_WAIT0()  asm volatile("cp.async.wait_group 0;" ::: "memory")

#define LDSM4(r0, r1, r2, r3, addr)                                          \
    asm volatile("ldmatrix.sync.aligned.m8n8.x4.shared.b16 {%0,%1,%2,%3}, [%4];" \
                 : "=r"(r0), "=r"(r1), "=r"(r2), "=r"(r3) : "r"(addr))
#define LDSM2(r0, r1, addr)                                                  \
    asm volatile("ldmatrix.sync.aligned.m8n8.x2.shared.b16 {%0,%1}, [%2];"   \
                 : "=r"(r0), "=r"(r1) : "r"(addr))

__device__ __forceinline__ void mma16816(float* c, const uint32_t* a, const uint32_t* b) {
    asm volatile(
        "mma.sync.aligned.m16n8k16.row.col.f32.bf16.bf16.f32 "
        "{%0,%1,%2,%3}, {%4,%5,%6,%7}, {%8,%9}, {%0,%1,%2,%3};"
        : "+f"(c[0]), "+f"(c[1]), "+f"(c[2]), "+f"(c[3])
        : "r"(a[0]), "r"(a[1]), "r"(a[2]), "r"(a[3]), "r"(b[0]), "r"(b[1]));
}

__device__ __forceinline__ uint32_t pack_bf16(float a, float b) {
    __nv_bfloat162 t = __floats2bfloat162_rn(a, b);
    return *(uint32_t*)&t;
}

// swizzled byte offset within a 128x32 bf16 tile (64B rows, 16B chunks) — GEMM
__device__ __forceinline__ uint32_t sw_off(int r, int c16) {
    return (uint32_t)(r * 64 + ((c16 ^ ((r >> 1) & 3)) << 4));
}
// swizzle for 128B rows (8 chunks) or 256B rows (16 chunks): x = c ^ (r&7)
__device__ __forceinline__ uint32_t sw128(int r, int c16) {
    return (uint32_t)(r * 128 + ((c16 ^ (r & 7)) << 4));
}
__device__ __forceinline__ uint32_t sw256(int r, int c16) {
    return (uint32_t)(r * 256 + ((c16 ^ (r & 7)) << 4));
}

// ---------------------------------------------------------------------------
// bf16-split tensor-core GEMM (unchanged from R3, proven)
// ---------------------------------------------------------------------------
#define GEMM_STAGE_BYTES 32768
#define GEMM_SMEM (3 * GEMM_STAGE_BYTES)
__global__ __launch_bounds__(256, 2)
void gemm_mma_kernel(const __nv_bfloat16* __restrict__ Ahi, const __nv_bfloat16* __restrict__ Alo,
                     const __nv_bfloat16* __restrict__ Bhi, const __nv_bfloat16* __restrict__ Blo,
                     const float* __restrict__ bias, float* __restrict__ C,
                     int M, int N, int K) {
    extern __shared__ char smraw[];
    const uint32_t sbase = smem_u32(smraw);
    const int tid = threadIdx.x;
    const int lane = tid & 31;
    const int warp = tid >> 5;
    const int wm = warp & 1;
    const int wn = warp >> 1;

    const int row0 = blockIdx.y * 128;
    const int col0 = blockIdx.x * 128;
    const __nv_bfloat16* srcs[4] = {Ahi + (size_t)row0 * K, Alo + (size_t)row0 * K,
                                    Bhi + (size_t)col0 * K, Blo + (size_t)col0 * K};
    const int nk = K / 32;

    auto load_stage = [&](int kc, int st) {
        const int kbase = kc * 32;
        const uint32_t stg = sbase + st * GEMM_STAGE_BYTES;
#pragma unroll
        for (int t = 0; t < 4; t++) {
            const __nv_bfloat16* s = srcs[t];
#pragma unroll
            for (int it = 0; it < 2; it++) {
                int idx = tid + it * 256;
                int r = idx >> 2, c = idx & 3;
                uint32_t dst = stg + t * 8192 + sw_off(r, c);
                CP_ASYNC16(dst, s + (size_t)r * K + kbase + c * 8);
            }
        }
    };

    float acc[4][4][4];
#pragma unroll
    for (int i = 0; i < 4; i++)
#pragma unroll
        for (int j = 0; j < 4; j++)
#pragma unroll
            for (int k = 0; k < 4; k++) acc[i][j][k] = 0.f;

    load_stage(0, 0); CP_COMMIT();
    load_stage(1, 1); CP_COMMIT();

    for (int kc = 0; kc < nk; kc++) {
        const int ps = kc + 2;
        if (ps < nk) load_stage(ps, ps % 3);
        CP_COMMIT();
        CP_WAIT2();
        __syncthreads();

        const uint32_t stg = sbase + (kc % 3) * GEMM_STAGE_BYTES;
        const uint32_t sAhi = stg, sAlo = stg + 8192, sBhi = stg + 16384, sBlo = stg + 24576;

#pragma unroll
        for (int ks = 0; ks < 2; ks++) {
            uint32_t ah[4][4], al[4][4], bf[4][2];
            const int arow = lane & 15;
            const int ac = ks * 2 + (lane >> 4);
            const int brow = lane & 7;
            const int bc = ks * 2 + ((lane >> 3) & 1);
#pragma unroll
            for (int mt = 0; mt < 4; mt++) {
                int r = wm * 64 + mt * 16 + arow;
                LDSM4(ah[mt][0], ah[mt][1], ah[mt][2], ah[mt][3], sAhi + sw_off(r, ac));
            }
#pragma unroll
            for (int mt = 0; mt < 4; mt++) {
                int r = wm * 64 + mt * 16 + arow;
                LDSM4(al[mt][0], al[mt][1], al[mt][2], al[mt][3], sAlo + sw_off(r, ac));
            }
#pragma unroll
            for (int nt = 0; nt < 4; nt++) {
                int r = wn * 32 + nt * 8 + brow;
                LDSM2(bf[nt][0], bf[nt][1], sBhi + sw_off(r, bc));
            }
#pragma unroll
            for (int mt = 0; mt < 4; mt++)
#pragma unroll
                for (int nt = 0; nt < 4; nt++) {
                    mma16816(acc[mt][nt], ah[mt], bf[nt]);
                    mma16816(acc[mt][nt], al[mt], bf[nt]);
                }
#pragma unroll
            for (int nt = 0; nt < 4; nt++) {
                int r = wn * 32 + nt * 8 + brow;
                LDSM2(bf[nt][0], bf[nt][1], sBlo + sw_off(r, bc));
            }
#pragma unroll
            for (int mt = 0; mt < 4; mt++)
#pragma unroll
                for (int nt = 0; nt < 4; nt++)
                    mma16816(acc[mt][nt], ah[mt], bf[nt]);
        }
        __syncthreads();
    }

#pragma unroll
    for (int mt = 0; mt < 4; mt++) {
        int r = row0 + wm * 64 + mt * 16 + (lane >> 2);
#pragma unroll
        for (int nt = 0; nt < 4; nt++) {
            int c = col0 + wn * 32 + nt * 8 + (lane & 3) * 2;
            float b0 = __ldg(bias + c), b1 = __ldg(bias + c + 1);
            float2 v0 = make_float2(acc[mt][nt][0] + b0, acc[mt][nt][1] + b1);
            float2 v1 = make_float2(acc[mt][nt][2] + b0, acc[mt][nt][3] + b1);
            *(float2*)(C + (size_t)r * N + c) = v0;
            *(float2*)(C + (size_t)(r + 8) * N + c) = v1;
        }
    }
}

// ---------------------------------------------------------------------------
// fp32 -> bf16 hi/lo split
// ---------------------------------------------------------------------------
__global__ __launch_bounds__(256)
void split_kernel(const float4* __restrict__ x, __nv_bfloat162* __restrict__ hi,
                  __nv_bfloat162* __restrict__ lo, int n4) {
    int i = blockIdx.x * 256 + threadIdx.x;
    if (i >= n4) return;
    float4 v = x[i];
    __nv_bfloat16 h0 = __float2bfloat16(v.x), h1 = __float2bfloat16(v.y);
    __nv_bfloat16 h2 = __float2bfloat16(v.z), h3 = __float2bfloat16(v.w);
    __nv_bfloat16 l0 = __float2bfloat16(v.x - __bfloat162float(h0));
    __nv_bfloat16 l1 = __float2bfloat16(v.y - __bfloat162float(h1));
    __nv_bfloat16 l2 = __float2bfloat16(v.z - __bfloat162float(h2));
    __nv_bfloat16 l3 = __float2bfloat16(v.w - __bfloat162float(h3));
    hi[2 * i] = __halves2bfloat162(h0, h1);
    hi[2 * i + 1] = __halves2bfloat162(h2, h3);
    lo[2 * i] = __halves2bfloat162(l0, l1);
    lo[2 * i + 1] = __halves2bfloat162(l2, l3);
}

// ---------------------------------------------------------------------------
// Q prep: g_q fp32 (B,S,HID) -> qhi/qlo [bh][sdup][vec]  (one block per b,s,d)
// ---------------------------------------------------------------------------
__global__ __launch_bounds__(256)
void qprep_kernel(const float* __restrict__ q, __nv_bfloat16* __restrict__ qhi,
                  __nv_bfloat16* __restrict__ qlo) {
    __shared__ float sm[1024];
    int bid = blockIdx.x;              // (b*512+s)*4 + d
    int d = bid & 3;
    int bs = bid >> 2;                 // b*512+s
    int b = bs >> 9, s = bs & 511;
    const float* src = q + (size_t)bs * HID + d * 1024;
    int tid = threadIdx.x;
    *(float4*)&sm[tid * 4] = *(const float4*)(src + tid * 4);
    __syncthreads();
    // idx = h*64 + v
    int h = tid >> 4;                  // tid*4 -> idx = tid*4 : h = (tid*4)>>6 = tid>>4
    int v = (tid * 4) & 63;
    size_t dst = ((size_t)(b * 16 + h) * SDUP + (s * 4 + d)) * VECD + v;
    float x0 = sm[(v + 0) * 16 + h], x1 = sm[(v + 1) * 16 + h];
    float x2 = sm[(v + 2) * 16 + h], x3 = sm[(v + 3) * 16 + h];
    __nv_bfloat16 h0 = __float2bfloat16(x0), h1 = __float2bfloat16(x1);
    __nv_bfloat16 h2 = __float2bfloat16(x2), h3 = __float2bfloat16(x3);
    *(__nv_bfloat162*)(qhi + dst) = __halves2bfloat162(h0, h1);
    *(__nv_bfloat162*)(qhi + dst + 2) = __halves2bfloat162(h2, h3);
    __nv_bfloat16 l0 = __float2bfloat16(x0 - __bfloat162float(h0));
    __nv_bfloat16 l1 = __float2bfloat16(x1 - __bfloat162float(h1));
    __nv_bfloat16 l2 = __float2bfloat16(x2 - __bfloat162float(h2));
    __nv_bfloat16 l3 = __float2bfloat16(x3 - __bfloat162float(h3));
    *(__nv_bfloat162*)(qlo + dst) = __halves2bfloat162(l0, l1);
    *(__nv_bfloat162*)(qlo + dst + 2) = __halves2bfloat162(l2, l3);
}

// ---------------------------------------------------------------------------
// KV prep: keys/vals [b,n, v*16+h] -> khi/klo [bh][n][v], vhi/vlo [bh][v][n]
// one block per (b,n)
// ---------------------------------------------------------------------------
__global__ __launch_bounds__(256)
void kvprep_kernel(const float* __restrict__ keys, const float* __restrict__ vals,
                   __nv_bfloat16* __restrict__ khi, __nv_bfloat16* __restrict__ klo,
                   __nv_bfloat16* __restrict__ vhi, __nv_bfloat16* __restrict__ vlo) {
    __shared__ float sk[1024], sv[1024];
    int bid = blockIdx.x;              // b*512+n
    int b = bid >> 9, n = bid & 511;
    int tid = threadIdx.x;
    *(float4*)&sk[tid * 4] = *(const float4*)(keys + (size_t)bid * 1024 + tid * 4);
    *(float4*)&sv[tid * 4] = *(const float4*)(vals + (size_t)bid * 1024 + tid * 4);
    __syncthreads();
    int h = tid >> 4;
    int v = (tid * 4) & 63;
    // K: [bh][n][v]
    {
        size_t dst = ((size_t)(b * 16 + h) * NKV + n) * VECD + v;
        float x0 = sk[(v + 0) * 16 + h], x1 = sk[(v + 1) * 16 + h];
        float x2 = sk[(v + 2) * 16 + h], x3 = sk[(v + 3) * 16 + h];
        __nv_bfloat16 h0 = __float2bfloat16(x0), h1 = __float2bfloat16(x1);
        __nv_bfloat16 h2 = __float2bfloat16(x2), h3 = __float2bfloat16(x3);
        *(__nv_bfloat162*)(khi + dst) = __halves2bfloat162(h0, h1);
        *(__nv_bfloat162*)(khi + dst + 2) = __halves2bfloat162(h2, h3);
        __nv_bfloat16 l0 = __float2bfloat16(x0 - __bfloat162float(h0));
        __nv_bfloat16 l1 = __float2bfloat16(x1 - __bfloat162float(h1));
        __nv_bfloat16 l2 = __float2bfloat16(x2 - __bfloat162float(h2));
        __nv_bfloat16 l3 = __float2bfloat16(x3 - __bfloat162float(h3));
        *(__nv_bfloat162*)(klo + dst) = __halves2bfloat162(l0, l1);
        *(__nv_bfloat162*)(klo + dst + 2) = __halves2bfloat162(l2, l3);
    }
    // V: [bh][v][n] (scalar scattered stores)
#pragma unroll
    for (int j = 0; j < 4; j++) {
        float x = sv[(v + j) * 16 + h];
        __nv_bfloat16 hh = __float2bfloat16(x);
        __nv_bfloat16 ll = __float2bfloat16(x - __bfloat162float(hh));
        size_t dst = ((size_t)(b * 16 + h) * VECD + (v + j)) * NKV + n;
        vhi[dst] = hh;
        vlo[dst] = ll;
    }
}

// ---------------------------------------------------------------------------
// Tensor-core flash attention with bf16 hi/lo split.
// CTA: 256 thr (8 warps), 128 q-rows per CTA, online softmax over 4 chunks of 128.
// grid = (16 tiles, 64 bh)
// ---------------------------------------------------------------------------
#define ATT_SMEM (6 * 16384)
__global__ __launch_bounds__(256)
void attn_mma_kernel(const __nv_bfloat16* __restrict__ qhi, const __nv_bfloat16* __restrict__ qlo,
                     const __nv_bfloat16* __restrict__ khi, const __nv_bfloat16* __restrict__ klo,
                     const __nv_bfloat16* __restrict__ vhi, const __nv_bfloat16* __restrict__ vlo,
                     float* __restrict__ outT) {
    extern __shared__ char smraw[];
    const uint32_t sQhi = smem_u32(smraw);
    const uint32_t sQlo = sQhi + 16384;
    const uint32_t sKhi = sQhi + 32768;
    const uint32_t sKlo = sQhi + 49152;
    const uint32_t sVhi = sQhi + 65536;
    const uint32_t sVlo = sQhi + 81920;

    const int tid = threadIdx.x;
    const int lane = tid & 31;
    const int warp = tid >> 5;
    const int g = lane >> 2;        // row-in-8
    const int tq = lane & 3;        // col pair select
    const int bh = blockIdx.y;
    const int tile = blockIdx.x;
    const int wrow0 = warp * 16;

    // ---- load Q tile (async) ----
    const __nv_bfloat16* qh = qhi + ((size_t)bh * SDUP + tile * 128) * VECD;
    const __nv_bfloat16* ql = qlo + ((size_t)bh * SDUP + tile * 128) * VECD;
#pragma unroll
    for (int it = 0; it < 4; it++) {
        int idx = tid + it * 256;   // 0..1023
        int r = idx >> 3, c = idx & 7;
        CP_ASYNC16(sQhi + sw128(r, c), qh + (size_t)r * VECD + c * 8);
        CP_ASYNC16(sQlo + sw128(r, c), ql + (size_t)r * VECD + c * 8);
    }
    CP_COMMIT();

    const __nv_bfloat16* kh = khi + (size_t)bh * NKV * VECD;
    const __nv_bfloat16* kl = klo + (size_t)bh * NKV * VECD;
    const __nv_bfloat16* vh = vhi + (size_t)bh * VECD * NKV;
    const __nv_bfloat16* vl = vlo + (size_t)bh * VECD * NKV;

    float oa[8][4];
#pragma unroll
    for (int i = 0; i < 8; i++)
#pragma unroll
        for (int j = 0; j < 4; j++) oa[i][j] = 0.f;
    float m0 = -1e30f, m1 = -1e30f, l0 = 0.f, l1 = 0.f;

    for (int ck = 0; ck < 4; ck++) {
        const int n0 = ck * 128;
        __syncthreads();    // previous chunk compute done before overwrite
        // load K chunk [128][64] and V chunk [64][128]
#pragma unroll
        for (int it = 0; it < 4; it++) {
            int idx = tid + it * 256;
            int r = idx >> 3, c = idx & 7;
            CP_ASYNC16(sKhi + sw128(r, c), kh + (size_t)(n0 + r) * VECD + c * 8);
            CP_ASYNC16(sKlo + sw128(r, c), kl + (size_t)(n0 + r) * VECD + c * 8);
            int v = idx >> 4, cc = idx & 15;
            CP_ASYNC16(sVhi + sw256(v, cc), vh + (size_t)v * NKV + n0 + cc * 8);
            CP_ASYNC16(sVlo + sw256(v, cc), vl + (size_t)v * NKV + n0 + cc * 8);
        }
        CP_COMMIT();
        CP_WAIT0();
        __syncthreads();

        // ---- S = q k^T (3-product split) ----
        float S[16][4];
#pragma unroll
        for (int jt = 0; jt < 16; jt++)
#pragma unroll
            for (int j = 0; j < 4; j++) S[jt][j] = 0.f;

#pragma unroll
        for (int ks = 0; ks < 4; ks++) {
            uint32_t ah[4], al[4];
            int arow = wrow0 + (lane & 15);
            int ac = ks * 2 + (lane >> 4);
            uint32_t qoff = sw128(arow, ac);
            LDSM4(ah[0], ah[1], ah[2], ah[3], sQhi + qoff);
            LDSM4(al[0], al[1], al[2], al[3], sQlo + qoff);
#pragma unroll
            for (int jt = 0; jt < 16; jt++) {
                int brow = jt * 8 + (lane & 7);
                int bc = ks * 2 + ((lane >> 3) & 1);
                uint32_t koff = sw128(brow, bc);
                uint32_t b2h[2], b2l[2];
                LDSM2(b2h[0], b2h[1], sKhi + koff);
                LDSM2(b2l[0], b2l[1], sKlo + koff);
                mma16816(S[jt], ah, b2h);
                mma16816(S[jt], al, b2h);
                mma16816(S[jt], ah, b2l);
            }
        }

        // ---- online softmax ----
        float cm0 = -1e30f, cm1 = -1e30f;
#pragma unroll
        for (int jt = 0; jt < 16; jt++) {
            S[jt][0] *= 0.125f; S[jt][1] *= 0.125f;
            S[jt][2] *= 0.125f; S[jt][3] *= 0.125f;
            cm0 = fmaxf(cm0, fmaxf(S[jt][0], S[jt][1]));
            cm1 = fmaxf(cm1, fmaxf(S[jt][2], S[jt][3]));
        }
        cm0 = fmaxf(cm0, __shfl_xor_sync(0xffffffffu, cm0, 1));
        cm0 = fmaxf(cm0, __shfl_xor_sync(0xffffffffu, cm0, 2));
        cm1 = fmaxf(cm1, __shfl_xor_sync(0xffffffffu, cm1, 1));
        cm1 = fmaxf(cm1, __shfl_xor_sync(0xffffffffu, cm1, 2));
        float mn0 = fmaxf(m0, cm0), mn1 = fmaxf(m1, cm1);
        float sc0 = __expf(m0 - mn0), sc1 = __expf(m1 - mn1);
        m0 = mn0; m1 = mn1;
        l0 *= sc0; l1 *= sc1;
#pragma unroll
        for (int vt = 0; vt < 8; vt++) {
            oa[vt][0] *= sc0; oa[vt][1] *= sc0;
            oa[vt][2] *= sc1; oa[vt][3] *= sc1;
        }

        // ---- P = exp(S - m), split to bf16 hi/lo, P@V fused ----
        float cs0 = 0.f, cs1 = 0.f;
#pragma unroll
        for (int ks = 0; ks < 8; ks++) {
            uint32_t pah[4], pal[4];
#pragma unroll
            for (int half = 0; half < 2; half++) {
                int jt = ks * 2 + half;
                float p0 = __expf(S[jt][0] - m0);
                float p1 = __expf(S[jt][1] - m0);
                float p2 = __expf(S[jt][2] - m1);
                float p3 = __expf(S[jt][3] - m1);
                cs0 += p0 + p1;
                cs1 += p2 + p3;
                float h0 = __bfloat162float(__float2bfloat16(p0));
                float h1 = __bfloat162float(__float2bfloat16(p1));
                float h2 = __bfloat162float(__float2bfloat16(p2));
                float h3 = __bfloat162float(__float2bfloat16(p3));
                pah[half * 2 + 0] = pack_bf16(h0, h1);
                pah[half * 2 + 1] = pack_bf16(h2, h3);
                pal[half * 2 + 0] = pack_bf16(p0 - h0, p1 - h1);
                pal[half * 2 + 1] = pack_bf16(p2 - h2, p3 - h3);
            }
            // wait: frag order must be a0=rowg k0-7 half... reorder:
            // pah currently {h0h1(half0), h2h3(half0), h0h1(half1), h2h3(half1)} == {a0,a1,a2,a3} ✓
#pragma unroll
            for (int vt = 0; vt < 8; vt++) {
                int brow = vt * 8 + (lane & 7);
                int bc = ks * 2 + ((lane >> 3) & 1);
                uint32_t voff = sw256(brow, bc);
                uint32_t b2h[2], b2l[2];
                LDSM2(b2h[0], b2h[1], sVhi + voff);
                LDSM2(b2l[0], b2l[1], sVlo + voff);
                mma16816(oa[vt], pah, b2h);
                mma16816(oa[vt], pal, b2h);
                mma16816(oa[vt], pah, b2l);
            }
        }
        cs0 += __shfl_xor_sync(0xffffffffu, cs0, 1);
        cs0 += __shfl_xor_sync(0xffffffffu, cs0, 2);
        cs1 += __shfl_xor_sync(0xffffffffu, cs1, 1);
        cs1 += __shfl_xor_sync(0xffffffffu, cs1, 2);
        l0 += cs0; l1 += cs1;
    }

    // ---- epilogue ----
    float inv0 = 1.f / l0, inv1 = 1.f / l1;
    float* orow0 = outT + ((size_t)bh * SDUP + tile * 128 + wrow0 + g) * VECD;
    float* orow1 = orow0 + 8 * VECD;
#pragma unroll
    for (int vt = 0; vt < 8; vt++) {
        int v = vt * 8 + tq * 2;
        *(float2*)(orow0 + v) = make_float2(oa[vt][0] * inv0, oa[vt][1] * inv0);
        *(float2*)(orow1 + v) = make_float2(oa[vt][2] * inv1, oa[vt][3] * inv1);
    }
}

// ---------------------------------------------------------------------------
// LayerNorm: gathers from attnT [bh][sdup][vec], outputs bf16 hi/lo [row][HID]
// ---------------------------------------------------------------------------
__global__ __launch_bounds__(256)
void ln_gather_split_kernel(const float* __restrict__ attnT, const float* __restrict__ gam,
                            const float* __restrict__ bet, __nv_bfloat16* __restrict__ hi,
                            __nv_bfloat16* __restrict__ lo) {
    __shared__ float xs[HID];
    __shared__ float red[8];
    __shared__ float red2[8];
    const int row = blockIdx.x;        // b*512+s
    const int b = row >> 9, s = row & 511;
    const int tid = threadIdx.x;
    const int lane = tid & 31, w = tid >> 5;

    float lsum = 0.f;
#pragma unroll
    for (int it = 0; it < 4; it++) {
        int i = it * 1024 + tid * 4;
        int h = i >> 8, d = (i >> 6) & 3, v = i & 63;
        const float* src = attnT + ((size_t)(b * 16 + h) * SDUP + (s * 4 + d)) * VECD + v;
        float4 x = *(const float4*)src;
        *(float4*)&xs[i] = x;
        lsum += x.x + x.y + x.z + x.w;
    }
#pragma unroll
    for (int o = 16; o > 0; o >>= 1) lsum += __shfl_xor_sync(0xffffffffu, lsum, o);
    if (lane == 0) red[w] = lsum;
    __syncthreads();
    float tot = 0.f;
#pragma unroll
    for (int j = 0; j < 8; j++) tot += red[j];
    float mu = tot * (1.f / HID);

    float lv = 0.f;
    for (int i = tid; i < HID; i += 256) {
        float d = xs[i] - mu;
        lv += d * d;
    }
#pragma unroll
    for (int o = 16; o > 0; o >>= 1) lv += __shfl_xor_sync(0xffffffffu, lv, o);
    if (lane == 0) red2[w] = lv;
    __syncthreads();
    float tv = 0.f;
#pragma unroll
    for (int j = 0; j < 8; j++) tv += red2[j];
    float inv = rsqrtf(tv * (1.f / HID) + 1e-12f);

#pragma unroll
    for (int it = 0; it < 4; it++) {
        int i = it * 1024 + tid * 4;
        float4 xv = *(const float4*)&xs[i];
        float4 gv = *(const float4*)&gam[i];
        float4 bv = *(const float4*)&bet[i];
        float y0 = (xv.x - mu) * inv * gv.x + bv.x;
        float y1 = (xv.y - mu) * inv * gv.y + bv.y;
        float y2 = (xv.z - mu) * inv * gv.z + bv.z;
        float y3 = (xv.w - mu) * inv * gv.w + bv.w;
        __nv_bfloat16 h0 = __float2bfloat16(y0), h1 = __float2bfloat16(y1);
        __nv_bfloat16 h2 = __float2bfloat16(y2), h3 = __float2bfloat16(y3);
        __nv_bfloat16 l0 = __float2bfloat16(y0 - __bfloat162float(h0));
        __nv_bfloat16 l1 = __float2bfloat16(y1 - __bfloat162float(h1));
        __nv_bfloat16 l2 = __float2bfloat16(y2 - __bfloat162float(h2));
        __nv_bfloat16 l3 = __float2bfloat16(y3 - __bfloat162float(h3));
        size_t o = (size_t)row * HID + i;
        *(__nv_bfloat162*)(hi + o) = __halves2bfloat162(h0, h1);
        *(__nv_bfloat162*)(hi + o + 2) = __halves2bfloat162(h2, h3);
        *(__nv_bfloat162*)(lo + o) = __halves2bfloat162(l0, l1);
        *(__nv_bfloat162*)(lo + o + 2) = __halves2bfloat162(l2, l3);
    }
}

// ---------------------------------------------------------------------------
extern "C" void kernel_launch(void* const* d_in, const int* in_sizes, int n_in,
                              void* d_out, int out_size) {
    const float* emb  = (const float*)d_in[0];
    const float* keys = (const float*)d_in[1];
    const float* vals = (const float*)d_in[2];
    const float* Wq   = (const float*)d_in[3];
    const float* bq   = (const float*)d_in[4];
    const float* Wre  = (const float*)d_in[5];
    const float* bre  = (const float*)d_in[6];
    const float* ln_g = (const float*)d_in[7];
    const float* ln_b = (const float*)d_in[8];
    float* out = (float*)d_out;

    float *qbuf, *aT;
    __nv_bfloat16 *ehi, *elo, *lnhi, *lnlo, *wqhi, *wqlo, *wrehi, *wrelo;
    __nv_bfloat16 *qhi, *qlo, *khi, *klo, *vhi, *vlo;
    cudaGetSymbolAddress((void**)&qbuf, g_q);
    cudaGetSymbolAddress((void**)&aT, g_attnT);
    cudaGetSymbolAddress((void**)&ehi, g_ehi);
    cudaGetSymbolAddress((void**)&elo, g_elo);
    cudaGetSymbolAddress((void**)&lnhi, g_lnhi);
    cudaGetSymbolAddress((void**)&lnlo, g_lnlo);
    cudaGetSymbolAddress((void**)&wqhi, g_wqhi);
    cudaGetSymbolAddress((void**)&wqlo, g_wqlo);
    cudaGetSymbolAddress((void**)&wrehi, g_wrehi);
    cudaGetSymbolAddress((void**)&wrelo, g_wrelo);
    cudaGetSymbolAddress((void**)&qhi, g_qhi);
    cudaGetSymbolAddress((void**)&qlo, g_qlo);
    cudaGetSymbolAddress((void**)&khi, g_khi);
    cudaGetSymbolAddress((void**)&klo, g_klo);
    cudaGetSymbolAddress((void**)&vhi, g_vhi);
    cudaGetSymbolAddress((void**)&vlo, g_vlo);

    cudaFuncSetAttribute(gemm_mma_kernel, cudaFuncAttributeMaxDynamicSharedMemorySize, GEMM_SMEM);
    cudaFuncSetAttribute(attn_mma_kernel, cudaFuncAttributeMaxDynamicSharedMemorySize, ATT_SMEM);

    // input splits
    split_kernel<<<(MROWS * HID / 4 + 255) / 256, 256>>>((const float4*)emb,
        (__nv_bfloat162*)ehi, (__nv_bfloat162*)elo, MROWS * HID / 4);
    split_kernel<<<(HID * HID / 4 + 255) / 256, 256>>>((const float4*)Wq,
        (__nv_bfloat162*)wqhi, (__nv_bfloat162*)wqlo, HID * HID / 4);
    split_kernel<<<(HID * HID / 4 + 255) / 256, 256>>>((const float4*)Wre,
        (__nv_bfloat162*)wrehi, (__nv_bfloat162*)wrelo, HID * HID / 4);
    // K/V relayout + split
    kvprep_kernel<<<4 * NKV, 256>>>(keys, vals, khi, klo, vhi, vlo);
    // q projection
    gemm_mma_kernel<<<dim3(HID / 128, MROWS / 128), 256, GEMM_SMEM>>>(
        ehi, elo, wqhi, wqlo, bq, qbuf, MROWS, HID, HID);
    // q relayout + split
    qprep_kernel<<<MROWS * 4, 256>>>(qbuf, qhi, qlo);
    // attention (tensor cores)
    attn_mma_kernel<<<dim3(16, 64), 256, ATT_SMEM>>>(qhi, qlo, khi, klo, vhi, vlo, aT);
    // layernorm gather + split
    ln_gather_split_kernel<<<MROWS, 256>>>(aT, ln_g, ln_b, lnhi, lnlo);
    // output projection
    gemm_mma_kernel<<<dim3(HID / 128, MROWS / 128), 256, GEMM_SMEM>>>(
        lnhi, lnlo, wrehi, wrelo, bre, out, MROWS, HID, HID);
}